// round 15
// baseline (speedup 1.0000x reference)
#include <cuda_runtime.h>
#include <cuda_bf16.h>
#include <mma.h>
#include <math.h>
#include <stdint.h>

using namespace nvcuda;

// Problem constants
#define BATCH   256
#define IN_DIM  512
#define OUT_DIM 512
#define KORD    3
#define GN      23
#define NB      19

// GEMM geometry
#define KSLOT   24
#define KTOT    (IN_DIM * KSLOT)        // 12288
#define MT      128
#define NT      128
#define KSPLIT  16
#define KLOCAL  (KTOT / KSPLIT)         // 768
#define KC      64
#define NCHUNK  (KLOCAL / KC)           // 12
#define RSW     72                      // smem row stride in bf16 (144B)
#define NSTAGE  4

// Static device scratch (R8 layouts)
// g_Bmat:  [b][i*24+g]  row-major
// g_coefT: [o][i*24+g]  row-major
__device__ __nv_bfloat16 g_Bmat [BATCH * KTOT];
__device__ __nv_bfloat16 g_coefT[OUT_DIM * KTOT];
__device__ float         g_part [KSPLIT * BATCH * OUT_DIM];

#define PF_SMEM 53248   // 4KB msc + 48KB T + pad

__device__ __forceinline__ uint32_t smem_u32(const void* p) {
    uint32_t a;
    asm("{ .reg .u64 t; cvta.to.shared.u64 t, %1; cvt.u32.u64 %0, t; }"
        : "=r"(a) : "l"(p));
    return a;
}
__device__ __forceinline__ void cp_async16(uint32_t dst, const void* src) {
    asm volatile("cp.async.cg.shared.global [%0], [%1], 16;" :: "r"(dst), "l"(src));
}
__device__ __forceinline__ unsigned bf16x2_of(float hi, float lo) {
    unsigned u;
    asm("cvt.rn.bf16x2.f32 %0, %1, %2;" : "=r"(u) : "f"(hi), "f"(lo));
    return u;
}

// ---------------------------------------------------------------------------
// Fused kernel A: blocks [0,512) = prep, [512,768) = fold (prep-first order,
// per the R8/R11 experiment). Dynamic smem (53.25 KB).
// ---------------------------------------------------------------------------
__device__ void prep_impl(unsigned char* sbuf, int bx,
                          const float* __restrict__ x,
                          const float* __restrict__ grid)
{
    float (*Gs)[25] = (float(*)[25])sbuf;   // 3200 B

    const int i0 = (bx & 15) * 32;
    const int b0 = (bx >> 4) * 8;
    const int t    = threadIdx.x;
    const int lane = t & 31;   // i_local
    const int row  = t >> 5;   // b_local

    for (int k = t; k < 32 * GN; k += 256) {
        const int r = k / GN, c = k - r * GN;
        Gs[r][c] = grid[(size_t)(i0 + r) * GN + c];
    }
    const float xv = x[(size_t)(b0 + row) * IN_DIM + i0 + lane];
    __syncthreads();

    const float* G = Gs[lane];
    const float base = xv / (1.0f + __expf(-xv));

    // fast interval index + comparison fixup (matches reference semantics)
    int m = -1;
    if (xv >= G[0] && xv < G[GN - 1]) {
        m = (int)((xv - G[0]) * __frcp_rn(G[1] - G[0]));
        if (m < 0) m = 0;
        if (m > GN - 2) m = GN - 2;
        while (m > 0 && xv < G[m]) --m;
        while (m < GN - 2 && xv >= G[m + 1]) ++m;
    }

    float bv0 = 0.f, bv1 = 0.f, bv2 = 0.f, bv3 = 0.f;
    int j = 0;
    if (m >= 0) {
        auto gg = [&](int idx) -> float {
            idx = idx < 0 ? 0 : (idx > GN - 1 ? GN - 1 : idx);
            return G[idx];
        };
        float bv[4]; float lft[4], rgt[4];
        bv[0] = 1.0f;
        #pragma unroll
        for (int kk = 1; kk <= KORD; kk++) {
            lft[kk] = xv - gg(m + 1 - kk);
            rgt[kk] = gg(m + kk) - xv;
            float saved = 0.0f;
            #pragma unroll
            for (int r = 0; r < KORD; r++) {
                if (r >= kk) break;
                const float temp = bv[r] / (rgt[r + 1] + lft[kk - r]);
                bv[r] = saved + rgt[r + 1] * temp;
                saved = lft[kk - r] * temp;
            }
            bv[kk] = saved;
        }
        j = m - KORD;
        if (j < 0) j = 0;
        if (j > NB - 4) j = NB - 4;
        float w[4];
        #pragma unroll
        for (int tt = 0; tt < 4; tt++) {
            const int r = j + tt;
            const bool valid = (r >= m - KORD) && (r <= m) && (r >= 0) && (r <= NB - 1);
            w[tt] = valid ? bv[r - (m - KORD)] : 0.0f;
        }
        bv0 = w[0]; bv1 = w[1]; bv2 = w[2]; bv3 = w[3];
    }

    const float hi = __bfloat162float(__float2bfloat16(base));
    const float lo = base - hi;

    // register-select pack: word p holds slots {2p (low), 2p+1 (high)}
    const unsigned p01 = bf16x2_of(bv1, bv0);
    const unsigned p23 = bf16x2_of(bv3, bv2);
    const unsigned q0  = p01 << 16;                       // [bv0 : 0]
    const unsigned q12 = (p01 >> 16) | (p23 << 16);       // [bv2 : bv1]
    const unsigned q3  = p23 >> 16;                       // [0   : bv3]
    const bool ev = (j & 1) == 0;
    const unsigned va = ev ? p01 : q0;
    const unsigned vb = ev ? p23 : q12;
    const unsigned vc = ev ? 0u  : q3;
    const int jh = j >> 1;

    unsigned uw[12];
    #pragma unroll
    for (int p = 0; p < 10; p++)
        uw[p] = (p == jh) ? va : (p == jh + 1) ? vb : (p == jh + 2) ? vc : 0u;
    uw[10] = bf16x2_of(lo, base);   // slots 20 (base), 21 (lo)
    uw[11] = 0u;                    // slots 22, 23

    uint4* dst = (uint4*)((char*)g_Bmat + (size_t)(b0 + row) * (KTOT * 2)
                          + (size_t)(i0 + lane) * (KSLOT * 2));
    dst[0] = make_uint4(uw[0], uw[1], uw[2],  uw[3]);
    dst[1] = make_uint4(uw[4], uw[5], uw[6],  uw[7]);
    dst[2] = make_uint4(uw[8], uw[9], uw[10], uw[11]);
}

// fold: 32 i x 32 o tile, float4 coef reads, T-staged coalesced writeout.
// T[ol][il*24+g] bf16; output row (o0+ol) gets 32*24=768 bf16 = 1536B chunk.
__device__ void fold_impl(unsigned char* sbuf, int bx,
                          const float* __restrict__ coef,
                          const float* __restrict__ scale_sp,
                          const float* __restrict__ mask)
{
    float* msc = (float*)sbuf;                                   // 4096 B
    __nv_bfloat16 (*T)[32 * KSLOT] =
        (__nv_bfloat16(*)[32 * KSLOT])(sbuf + 4096);             // 49152 B

    const int i0 = (bx & 15) * 32;
    const int o0 = (bx >> 4) * 32;
    const int t  = threadIdx.x;

    // masks, msc, T special slots (19..23) per (il,ol)
    #pragma unroll
    for (int rr = 0; rr < 4; rr++) {
        const int id = t + rr * 256;
        const int il = id >> 5, ol = id & 31;
        const size_t io = (size_t)(i0 + il) * OUT_DIM + o0 + ol;
        const float mk = mask[io];
        msc[id] = mk * scale_sp[io];
        const __nv_bfloat16 mb = __float2bfloat16(mk);
        const __nv_bfloat16 zb = __float2bfloat16(0.0f);
        __nv_bfloat16* tp = &T[ol][il * KSLOT];
        tp[19] = zb; tp[20] = mb; tp[21] = mb; tp[22] = zb; tp[23] = zb;
    }
    __syncthreads();

    // convert: 19456 floats = 4864 float4, 19 per thread, coalesced LDG.128
    #pragma unroll
    for (int k = 0; k < 19; k++) {
        const int u4 = t + k * 256;           // < 4864 exactly
        const int il = u4 / 152;              // 152 float4 per il row-block
        const int r4 = u4 - il * 152;
        const float4 cv = *(const float4*)(coef
            + (size_t)(i0 + il) * (OUT_DIM * NB) + o0 * NB + r4 * 4);
        const int e0 = r4 * 4;
        int ol = e0 / 19;
        int g  = e0 - 19 * ol;
        const float vals[4] = {cv.x, cv.y, cv.z, cv.w};
        #pragma unroll
        for (int q = 0; q < 4; q++) {
            T[ol][il * KSLOT + g] = __float2bfloat16(vals[q] * msc[il * 32 + ol]);
            if (++g == NB) { g = 0; ++ol; }
        }
    }
    __syncthreads();

    // writeout: 32 rows x 96 uint4; 8 threads per row, 12 uint4 each
    const int ol  = t >> 3;
    const int sub = t & 7;
    uint4* dst = (uint4*)((char*)g_coefT + (size_t)(o0 + ol) * (KTOT * 2)
                          + (size_t)i0 * (KSLOT * 2));
    const uint4* src = (const uint4*)&T[ol][0];
    #pragma unroll
    for (int k = 0; k < 12; k++) dst[sub + k * 8] = src[sub + k * 8];
}

__global__ __launch_bounds__(256) void kan_prep_fold_kernel(
    const float* __restrict__ x, const float* __restrict__ grid,
    const float* __restrict__ coef, const float* __restrict__ scale_sp,
    const float* __restrict__ mask)
{
    extern __shared__ __align__(16) unsigned char sbuf[];
    const int bx = blockIdx.x;
    if (bx < 512) prep_impl(sbuf, bx, x, grid);
    else          fold_impl(sbuf, bx - 512, coef, scale_sp, mask);
}

// ---------------------------------------------------------------------------
// Kernel B: bf16 wmma GEMM, 4-stage cp.async pipeline, K-split. (R8 exact)
// ---------------------------------------------------------------------------
#define TILE_B   (128 * RSW * 2)                 // 18432 B per matrix tile
#define STAGE_B  (2 * TILE_B)
#define SM_TOTAL (NSTAGE * STAGE_B)              // 147456 B

__global__ __launch_bounds__(256) void kan_gemm_kernel()
{
    extern __shared__ char smem[];
    const uint32_t sb = smem_u32(smem);
    const int t = threadIdx.x;

    const int m0 = blockIdx.x * MT;
    const int n0 = blockIdx.y * NT;
    const int kbase0 = blockIdx.z * KLOCAL;

    const int wid = t >> 5;
    const int wm  = wid & 1;
    const int wn  = wid >> 1;

    auto load_chunk = [&](int c, int stage) {
        const int kb = kbase0 + c * KC;
        const uint32_t so = sb + stage * STAGE_B;
        #pragma unroll
        for (int it = 0; it < 4; it++) {
            const int unit = t + it * 256;
            const int r = unit >> 3, c16 = unit & 7;
            cp_async16(so + r * (RSW * 2) + c16 * 16,
                       g_Bmat + (size_t)(m0 + r) * KTOT + kb + c16 * 8);
        }
        #pragma unroll
        for (int it = 0; it < 4; it++) {
            const int unit = t + it * 256;
            const int r = unit >> 3, c16 = unit & 7;
            cp_async16(so + TILE_B + r * (RSW * 2) + c16 * 16,
                       g_coefT + (size_t)(n0 + r) * KTOT + kb + c16 * 8);
        }
        asm volatile("cp.async.commit_group;" ::: "memory");
    };

    wmma::fragment<wmma::accumulator, 16, 16, 16, float> cf[4][2];
    #pragma unroll
    for (int mi = 0; mi < 4; mi++)
        #pragma unroll
        for (int ni = 0; ni < 2; ni++)
            wmma::fill_fragment(cf[mi][ni], 0.0f);

    load_chunk(0, 0);
    load_chunk(1, 1);
    load_chunk(2, 2);

    for (int c = 0; c < NCHUNK; c++) {
        const int stage = c & (NSTAGE - 1);
        if (c + 3 < NCHUNK) {
            load_chunk(c + 3, (c + 3) & (NSTAGE - 1));
            asm volatile("cp.async.wait_group 3;" ::: "memory");
        } else if (c == NCHUNK - 3) {
            asm volatile("cp.async.wait_group 2;" ::: "memory");
        } else if (c == NCHUNK - 2) {
            asm volatile("cp.async.wait_group 1;" ::: "memory");
        } else {
            asm volatile("cp.async.wait_group 0;" ::: "memory");
        }
        __syncthreads();

        const __nv_bfloat16* At = (const __nv_bfloat16*)(smem + stage * STAGE_B);
        const __nv_bfloat16* Bt = (const __nv_bfloat16*)(smem + stage * STAGE_B + TILE_B);

        #pragma unroll
        for (int ks = 0; ks < KC / 16; ks++) {
            wmma::fragment<wmma::matrix_a, 16, 16, 16, __nv_bfloat16, wmma::row_major> af[4];
            wmma::fragment<wmma::matrix_b, 16, 16, 16, __nv_bfloat16, wmma::col_major> bf[2];
            #pragma unroll
            for (int mi = 0; mi < 4; mi++)
                wmma::load_matrix_sync(af[mi], At + (wm * 64 + mi * 16) * RSW + ks * 16, RSW);
            #pragma unroll
            for (int ni = 0; ni < 2; ni++)
                wmma::load_matrix_sync(bf[ni], Bt + (wn * 32 + ni * 16) * RSW + ks * 16, RSW);
            #pragma unroll
            for (int mi = 0; mi < 4; mi++)
                #pragma unroll
                for (int ni = 0; ni < 2; ni++)
                    wmma::mma_sync(cf[mi][ni], af[mi], bf[ni], cf[mi][ni]);
        }
        __syncthreads();
    }

    float* pbase = g_part + (size_t)blockIdx.z * (BATCH * OUT_DIM)
                 + (size_t)(m0 + wm * 64) * OUT_DIM + n0 + wn * 32;
    #pragma unroll
    for (int mi = 0; mi < 4; mi++)
        #pragma unroll
        for (int ni = 0; ni < 2; ni++)
            wmma::store_matrix_sync(pbase + (size_t)(mi * 16) * OUT_DIM + ni * 16,
                                    cf[mi][ni], OUT_DIM, wmma::mem_row_major);
}

// ---------------------------------------------------------------------------
// Kernel C: deterministic reduce over KSPLIT partials (float2 lanes, R8 exact).
// ---------------------------------------------------------------------------
__global__ __launch_bounds__(256) void kan_reduce_kernel(float* __restrict__ out)
{
    const int idx = blockIdx.x * 256 + threadIdx.x;     // 65536 float2 lanes
    const float2* p = (const float2*)g_part;
    float sx = 0.0f, sy = 0.0f;
    #pragma unroll
    for (int sp = 0; sp < KSPLIT; sp++) {
        const float2 v = p[(size_t)sp * (BATCH * OUT_DIM / 2) + idx];
        sx += v.x; sy += v.y;
    }
    ((float2*)out)[idx] = make_float2(sx, sy);
}

// ---------------------------------------------------------------------------
// Launch. Inputs: x, grid, coef, scale_sp, mask. Output fp32 [BATCH, OUT_DIM].
// ---------------------------------------------------------------------------
extern "C" void kernel_launch(void* const* d_in, const int* in_sizes, int n_in,
                              void* d_out, int out_size)
{
    const float* x        = (const float*)d_in[0];
    const float* grid     = (const float*)d_in[1];
    const float* coef     = (const float*)d_in[2];
    const float* scale_sp = (const float*)d_in[3];
    const float* mask     = (const float*)d_in[4];
    float* out = (float*)d_out;

    cudaFuncSetAttribute(kan_prep_fold_kernel,
                         cudaFuncAttributeMaxDynamicSharedMemorySize, PF_SMEM);
    cudaFuncSetAttribute(kan_gemm_kernel,
                         cudaFuncAttributeMaxDynamicSharedMemorySize, SM_TOTAL);

    kan_prep_fold_kernel<<<768, 256, PF_SMEM>>>(x, grid, coef, scale_sp, mask);

    dim3 gg(BATCH / MT, OUT_DIM / NT, KSPLIT);
    kan_gemm_kernel<<<gg, 256, SM_TOTAL>>>();

    kan_reduce_kernel<<<(BATCH * OUT_DIM / 2) / 256, 256>>>(out);
}

// round 17
// speedup vs baseline: 1.1929x; 1.1929x over previous
#include <cuda_runtime.h>
#include <cuda_bf16.h>
#include <mma.h>
#include <math.h>
#include <stdint.h>

using namespace nvcuda;

// Problem constants
#define BATCH   256
#define IN_DIM  512
#define OUT_DIM 512
#define KORD    3
#define GN      23
#define NB      19

// GEMM geometry
#define KSLOT   24
#define KTOT    (IN_DIM * KSLOT)        // 12288
#define MT      128
#define NT      128
#define KSPLIT  16
#define KLOCAL  (KTOT / KSPLIT)         // 768
#define KC      64
#define NCHUNK  (KLOCAL / KC)           // 12
#define RSW     72                      // smem row stride in bf16 (144B)
#define NSTAGE  4

// Static device scratch (R8 layouts)
__device__ __nv_bfloat16 g_Bmat [BATCH * KTOT];
__device__ __nv_bfloat16 g_coefT[OUT_DIM * KTOT];
__device__ float         g_part [KSPLIT * BATCH * OUT_DIM];

__device__ __forceinline__ uint32_t smem_u32(const void* p) {
    uint32_t a;
    asm("{ .reg .u64 t; cvta.to.shared.u64 t, %1; cvt.u32.u64 %0, t; }"
        : "=r"(a) : "l"(p));
    return a;
}
__device__ __forceinline__ void cp_async16(uint32_t dst, const void* src) {
    asm volatile("cp.async.cg.shared.global [%0], [%1], 16;" :: "r"(dst), "l"(src));
}
__device__ __forceinline__ unsigned bf16x2_of(float hi, float lo) {
    unsigned u;
    asm("cvt.rn.bf16x2.f32 %0, %1, %2;" : "=r"(u) : "f"(hi), "f"(lo));
    return u;
}

// ---------------------------------------------------------------------------
// Fused kernel A: blocks [0,512) = prep, [512,1024) = fold. Static 28.8KB
// sbuf (R8 occupancy conditions: 7 blocks/SM).
// ---------------------------------------------------------------------------
__device__ void prep_impl(unsigned char* sbuf, int bx,
                          const float* __restrict__ x,
                          const float* __restrict__ grid)
{
    float (*Gs)[25] = (float(*)[25])sbuf;   // 3200 B used

    const int i0 = (bx & 15) * 32;
    const int b0 = (bx >> 4) * 8;
    const int t    = threadIdx.x;
    const int lane = t & 31;   // i_local
    const int row  = t >> 5;   // b_local

    for (int k = t; k < 32 * GN; k += 256) {
        const int r = k / GN, c = k - r * GN;
        Gs[r][c] = grid[(size_t)(i0 + r) * GN + c];
    }
    const float xv = x[(size_t)(b0 + row) * IN_DIM + i0 + lane];
    __syncthreads();

    const float* G = Gs[lane];
    const float base = xv / (1.0f + __expf(-xv));

    // fast interval index + comparison fixup (matches reference semantics)
    int m = -1;
    if (xv >= G[0] && xv < G[GN - 1]) {
        m = (int)((xv - G[0]) * __frcp_rn(G[1] - G[0]));
        if (m < 0) m = 0;
        if (m > GN - 2) m = GN - 2;
        while (m > 0 && xv < G[m]) --m;
        while (m < GN - 2 && xv >= G[m + 1]) ++m;
    }

    float bv0 = 0.f, bv1 = 0.f, bv2 = 0.f, bv3 = 0.f;
    int j = 0;
    if (m >= 0) {
        auto gg = [&](int idx) -> float {
            idx = idx < 0 ? 0 : (idx > GN - 1 ? GN - 1 : idx);
            return G[idx];
        };
        float bv[4]; float lft[4], rgt[4];
        bv[0] = 1.0f;
        #pragma unroll
        for (int kk = 1; kk <= KORD; kk++) {
            lft[kk] = xv - gg(m + 1 - kk);
            rgt[kk] = gg(m + kk) - xv;
            float saved = 0.0f;
            #pragma unroll
            for (int r = 0; r < KORD; r++) {
                if (r >= kk) break;
                const float temp = bv[r] / (rgt[r + 1] + lft[kk - r]);
                bv[r] = saved + rgt[r + 1] * temp;
                saved = lft[kk - r] * temp;
            }
            bv[kk] = saved;
        }
        j = m - KORD;
        if (j < 0) j = 0;
        if (j > NB - 4) j = NB - 4;
        float w[4];
        #pragma unroll
        for (int tt = 0; tt < 4; tt++) {
            const int r = j + tt;
            const bool valid = (r >= m - KORD) && (r <= m) && (r >= 0) && (r <= NB - 1);
            w[tt] = valid ? bv[r - (m - KORD)] : 0.0f;
        }
        bv0 = w[0]; bv1 = w[1]; bv2 = w[2]; bv3 = w[3];
    }

    const float hi = __bfloat162float(__float2bfloat16(base));
    const float lo = base - hi;

    // register-select pack: word p holds slots {2p (low), 2p+1 (high)}
    const unsigned p01 = bf16x2_of(bv1, bv0);
    const unsigned p23 = bf16x2_of(bv3, bv2);
    const unsigned q0  = p01 << 16;                       // [bv0 : 0]
    const unsigned q12 = (p01 >> 16) | (p23 << 16);       // [bv2 : bv1]
    const unsigned q3  = p23 >> 16;                       // [0   : bv3]
    const bool ev = (j & 1) == 0;
    const unsigned va = ev ? p01 : q0;
    const unsigned vb = ev ? p23 : q12;
    const unsigned vc = ev ? 0u  : q3;
    const int jh = j >> 1;

    unsigned uw[12];
    #pragma unroll
    for (int p = 0; p < 10; p++)
        uw[p] = (p == jh) ? va : (p == jh + 1) ? vb : (p == jh + 2) ? vc : 0u;
    uw[10] = bf16x2_of(lo, base);   // slots 20 (base), 21 (lo)
    uw[11] = 0u;                    // slots 22, 23

    uint4* dst = (uint4*)((char*)g_Bmat + (size_t)(b0 + row) * (KTOT * 2)
                          + (size_t)(i0 + lane) * (KSLOT * 2));
    dst[0] = make_uint4(uw[0], uw[1], uw[2],  uw[3]);
    dst[1] = make_uint4(uw[4], uw[5], uw[6],  uw[7]);
    dst[2] = make_uint4(uw[8], uw[9], uw[10], uw[11]);
}

// fold (R8 exact — coalesced g-fastest reads, smem T staging, uint4 writeout)
__device__ void fold_impl(unsigned char* sbuf, int bx,
                          const float* __restrict__ coef,
                          const float* __restrict__ scale_sp,
                          const float* __restrict__ mask)
{
    float* msc = (float*)sbuf;                                   // 2048 B
    __nv_bfloat16 (*T)[16 * KSLOT] =
        (__nv_bfloat16(*)[16 * KSLOT])(sbuf + 2048);             // 24576 B

    const int i0 = (bx & 31) * 16;
    const int o0 = (bx >> 5) * 32;
    const int t  = threadIdx.x;

    #pragma unroll
    for (int rr = 0; rr < 2; rr++) {
        const int id = t + rr * 256;
        const int il = id >> 5, ol = id & 31;
        const size_t io = (size_t)(i0 + il) * OUT_DIM + o0 + ol;
        const float mk = mask[io];
        msc[id] = mk * scale_sp[io];
        const __nv_bfloat16 mb = __float2bfloat16(mk);
        const __nv_bfloat16 zb = __float2bfloat16(0.0f);
        T[ol][il * KSLOT + 19] = zb;
        T[ol][il * KSLOT + 20] = mb;
        T[ol][il * KSLOT + 21] = mb;
        T[ol][il * KSLOT + 22] = zb;
        T[ol][il * KSLOT + 23] = zb;
    }
    __syncthreads();

    #pragma unroll
    for (int k = 0; k < 38; k++) {
        const int lin = t + k * 256;            // < 9728 exactly
        const int il  = lin / 608;
        const int rem = lin - il * 608;
        const int ol  = rem / NB;
        const int g   = rem - ol * NB;
        const float v = coef[(size_t)(i0 + il) * (OUT_DIM * NB) + o0 * NB + rem]
                        * msc[il * 32 + ol];
        T[ol][il * KSLOT + g] = __float2bfloat16(v);
    }
    __syncthreads();

    const int ol  = t >> 3;
    const int sub = t & 7;
    uint4* dst = (uint4*)((char*)g_coefT + (size_t)(o0 + ol) * (KTOT * 2)
                          + (size_t)i0 * (KSLOT * 2));
    const uint4* src = (const uint4*)&T[ol][0];
    #pragma unroll
    for (int k = 0; k < 6; k++) dst[sub + k * 8] = src[sub + k * 8];
}

__global__ __launch_bounds__(256) void kan_prep_fold_kernel(
    const float* __restrict__ x, const float* __restrict__ grid,
    const float* __restrict__ coef, const float* __restrict__ scale_sp,
    const float* __restrict__ mask)
{
    __shared__ __align__(16) unsigned char sbuf[28800];
    const int bx = blockIdx.x;
    if (bx < 512) prep_impl(sbuf, bx, x, grid);
    else          fold_impl(sbuf, bx - 512, coef, scale_sp, mask);
}

// ---------------------------------------------------------------------------
// Kernel B: bf16 wmma GEMM, 4-stage cp.async pipeline, K-split.
// 128 threads = 4 warps in 2(M) x 2(N); warp tile 64x64 -> fragment-load
// smem amplification drops from (A:4x, B:2x) to (2x, 2x).
// ---------------------------------------------------------------------------
#define TILE_B   (128 * RSW * 2)                 // 18432 B per matrix tile
#define STAGE_B  (2 * TILE_B)
#define SM_TOTAL (NSTAGE * STAGE_B)              // 147456 B

__global__ __launch_bounds__(128) void kan_gemm_kernel()
{
    extern __shared__ char smem[];
    const uint32_t sb = smem_u32(smem);
    const int t = threadIdx.x;

    const int m0 = blockIdx.x * MT;
    const int n0 = blockIdx.y * NT;
    const int kbase0 = blockIdx.z * KLOCAL;

    const int wid = t >> 5;
    const int wm  = wid & 1;        // 64-row slab
    const int wn  = wid >> 1;       // 64-col slab

    auto load_chunk = [&](int c, int stage) {
        const int kb = kbase0 + c * KC;
        const uint32_t so = sb + stage * STAGE_B;
        #pragma unroll
        for (int it = 0; it < 8; it++) {
            const int unit = t + it * 128;
            const int r = unit >> 3, c16 = unit & 7;
            cp_async16(so + r * (RSW * 2) + c16 * 16,
                       g_Bmat + (size_t)(m0 + r) * KTOT + kb + c16 * 8);
        }
        #pragma unroll
        for (int it = 0; it < 8; it++) {
            const int unit = t + it * 128;
            const int r = unit >> 3, c16 = unit & 7;
            cp_async16(so + TILE_B + r * (RSW * 2) + c16 * 16,
                       g_coefT + (size_t)(n0 + r) * KTOT + kb + c16 * 8);
        }
        asm volatile("cp.async.commit_group;" ::: "memory");
    };

    wmma::fragment<wmma::accumulator, 16, 16, 16, float> cf[4][4];
    #pragma unroll
    for (int mi = 0; mi < 4; mi++)
        #pragma unroll
        for (int ni = 0; ni < 4; ni++)
            wmma::fill_fragment(cf[mi][ni], 0.0f);

    load_chunk(0, 0);
    load_chunk(1, 1);
    load_chunk(2, 2);

    for (int c = 0; c < NCHUNK; c++) {
        const int stage = c & (NSTAGE - 1);
        if (c + 3 < NCHUNK) {
            load_chunk(c + 3, (c + 3) & (NSTAGE - 1));
            asm volatile("cp.async.wait_group 3;" ::: "memory");
        } else if (c == NCHUNK - 3) {
            asm volatile("cp.async.wait_group 2;" ::: "memory");
        } else if (c == NCHUNK - 2) {
            asm volatile("cp.async.wait_group 1;" ::: "memory");
        } else {
            asm volatile("cp.async.wait_group 0;" ::: "memory");
        }
        __syncthreads();

        const __nv_bfloat16* At = (const __nv_bfloat16*)(smem + stage * STAGE_B);
        const __nv_bfloat16* Bt = (const __nv_bfloat16*)(smem + stage * STAGE_B + TILE_B);

        #pragma unroll
        for (int ks = 0; ks < KC / 16; ks++) {
            wmma::fragment<wmma::matrix_b, 16, 16, 16, __nv_bfloat16, wmma::col_major> bf[4];
            #pragma unroll
            for (int ni = 0; ni < 4; ni++)
                wmma::load_matrix_sync(bf[ni], Bt + (wn * 64 + ni * 16) * RSW + ks * 16, RSW);
            #pragma unroll
            for (int mi = 0; mi < 4; mi++) {
                wmma::fragment<wmma::matrix_a, 16, 16, 16, __nv_bfloat16, wmma::row_major> af;
                wmma::load_matrix_sync(af, At + (wm * 64 + mi * 16) * RSW + ks * 16, RSW);
                #pragma unroll
                for (int ni = 0; ni < 4; ni++)
                    wmma::mma_sync(cf[mi][ni], af, bf[ni], cf[mi][ni]);
            }
        }
        __syncthreads();
    }

    float* pbase = g_part + (size_t)blockIdx.z * (BATCH * OUT_DIM)
                 + (size_t)(m0 + wm * 64) * OUT_DIM + n0 + wn * 64;
    #pragma unroll
    for (int mi = 0; mi < 4; mi++)
        #pragma unroll
        for (int ni = 0; ni < 4; ni++)
            wmma::store_matrix_sync(pbase + (size_t)(mi * 16) * OUT_DIM + ni * 16,
                                    cf[mi][ni], OUT_DIM, wmma::mem_row_major);
}

// ---------------------------------------------------------------------------
// Kernel C: deterministic reduce over KSPLIT partials (float2 lanes, R8 exact).
// ---------------------------------------------------------------------------
__global__ __launch_bounds__(256) void kan_reduce_kernel(float* __restrict__ out)
{
    const int idx = blockIdx.x * 256 + threadIdx.x;     // 65536 float2 lanes
    const float2* p = (const float2*)g_part;
    float sx = 0.0f, sy = 0.0f;
    #pragma unroll
    for (int sp = 0; sp < KSPLIT; sp++) {
        const float2 v = p[(size_t)sp * (BATCH * OUT_DIM / 2) + idx];
        sx += v.x; sy += v.y;
    }
    ((float2*)out)[idx] = make_float2(sx, sy);
}

// ---------------------------------------------------------------------------
// Launch. Inputs: x, grid, coef, scale_sp, mask. Output fp32 [BATCH, OUT_DIM].
// ---------------------------------------------------------------------------
extern "C" void kernel_launch(void* const* d_in, const int* in_sizes, int n_in,
                              void* d_out, int out_size)
{
    const float* x        = (const float*)d_in[0];
    const float* grid     = (const float*)d_in[1];
    const float* coef     = (const float*)d_in[2];
    const float* scale_sp = (const float*)d_in[3];
    const float* mask     = (const float*)d_in[4];
    float* out = (float*)d_out;

    cudaFuncSetAttribute(kan_gemm_kernel,
                         cudaFuncAttributeMaxDynamicSharedMemorySize, SM_TOTAL);

    kan_prep_fold_kernel<<<1024, 256>>>(x, grid, coef, scale_sp, mask);

    dim3 gg(BATCH / MT, OUT_DIM / NT, KSPLIT);
    kan_gemm_kernel<<<gg, 128, SM_TOTAL>>>();

    kan_reduce_kernel<<<(BATCH * OUT_DIM / 2) / 256, 256>>>(out);
}